// round 15
// baseline (speedup 1.0000x reference)
#include <cuda_runtime.h>
#include <cuda_fp16.h>

#define N_MAX 100000
#define TPB   256
#define TPB_N 128

// Scratch (allocation-free rule: __device__ globals).
// fp16 rows of 8 (16B): slots 0..4 = features, 5..7 stay zero.
__device__ __align__(16) __half g_yh[N_MAX][8];    // pre-scaled features x*dinv (fp16)
__device__ __align__(16) __half g_aggh[N_MAX][8];  // layer-1 aggregation (fp16)
__device__ int   g_deg[N_MAX];                     // zero at entry (reset in k_prep)
__device__ float g_dinv[N_MAX];
__device__ float g_zs[N_MAX];                      // gather source (layer-2 scalar * dinv)
__device__ float g_a2[N_MAX];                      // RED target (layer-2 aggregation)
// NOTE: g_zs and g_a2 deliberately SEPARATE arrays — R13 showed colocating the
// gather source and RED target in one float2 costs ~7 us (same-sector contention).

// PDL: let the next grid launch early; wait gates on full predecessor completion.
#define PDL_LAUNCH() asm volatile("griddepcontrol.launch_dependents;" ::: "memory")
#define PDL_WAIT()   asm volatile("griddepcontrol.wait;" ::: "memory")

__device__ __forceinline__ unsigned h2_bits(__half2 h) {
    return *reinterpret_cast<unsigned*>(&h);
}

// One 128-bit vector half-precision reduction: 8 halves in a single op (4 LTS lanes).
__device__ __forceinline__ void red_add_v4_f16x2(void* addr, uint4 w) {
    asm volatile("red.global.add.noftz.v4.f16x2 [%0], {%1, %2, %3, %4};"
                 :: "l"(addr), "r"(w.x), "r"(w.y), "r"(w.z), "r"(w.w) : "memory");
}

// Degree: 4 edges per thread, int4 index loads (default cache policy — the
// index array is re-read by agg1/agg2, keep it L2-resident). Inputs only.
__global__ void k_degree(const int* __restrict__ dst, int E) {
    PDL_LAUNCH();
    int i = blockIdx.x * blockDim.x + threadIdx.x;
    int e0 = i * 4;
    if (e0 + 3 < E) {
        int4 d = *reinterpret_cast<const int4*>(dst + e0);
        atomicAdd(&g_deg[d.x], 1);
        atomicAdd(&g_deg[d.y], 1);
        atomicAdd(&g_deg[d.z], 1);
        atomicAdd(&g_deg[d.w], 1);
    } else {
        for (int e = e0; e < E; e++) atomicAdd(&g_deg[dst[e]], 1);
    }
}

// dinv, pre-scaled fp16 features, seed layer-1 agg with the self-loop term.
// Prelude (pre-wait): load x (pure input). Post-wait: read+reset g_deg.
__global__ void k_prep(const float* __restrict__ x, int n) {
    PDL_LAUNCH();
    int i = blockIdx.x * blockDim.x + threadIdx.x;
    if (i >= n) { PDL_WAIT(); return; }
    const float* xi = x + (long)i * 5;
    float x0 = xi[0], x1 = xi[1], x2 = xi[2], x3 = xi[3], x4 = xi[4];
    PDL_WAIT();
    float di = rsqrtf((float)(g_deg[i] + 1));   // +1 = self-loop
    g_deg[i] = 0;                               // restore for next launch (determinism)
    g_dinv[i] = di;
    __half2 p0 = __floats2half2_rn(x0 * di, x1 * di);
    __half2 p1 = __floats2half2_rn(x2 * di, x3 * di);
    __half2 p2 = __floats2half2_rn(x4 * di, 0.f);
    uint4 w = make_uint4(h2_bits(p0), h2_bits(p1), h2_bits(p2), 0u);
    *reinterpret_cast<uint4*>(&g_yh[i][0])   = w;
    *reinterpret_cast<uint4*>(&g_aggh[i][0]) = w;   // seed = self-loop
}

// Layer-1 aggregation: 1 edge/thread (LTS-lane floor config).
// Prelude: index loads (L2 hits after k_degree warmed them) overlap k_prep's tail.
__global__ void k_agg1(const int* __restrict__ ei, int E) {
    PDL_LAUNCH();
    int e = blockIdx.x * blockDim.x + threadIdx.x;
    if (e >= E) { PDL_WAIT(); return; }
    int s = ei[e];                   // src  (input, pre-wait)
    int d = ei[E + e];               // dst  (input, pre-wait)
    PDL_WAIT();
    uint4 w = *reinterpret_cast<const uint4*>(&g_yh[s][0]);  // 16B gather, 1 wavefront
    red_add_v4_f16x2(&g_aggh[d][0], w);                      // 1 RED, 4 LTS lanes
}

// Per-node: finish layer-1 norm (x dinv), 5->16 GEMM + bias + relu, 16->1 GEMM.
// Prelude: stage weights in smem (pure inputs) while agg1 drains.
__global__ void k_node(const float* __restrict__ W1, const float* __restrict__ b1,
                       const float* __restrict__ W2, int n) {
    PDL_LAUNCH();
    __shared__ float sW1[80];
    __shared__ float sb1[16];
    __shared__ float sW2[16];
    int t = threadIdx.x;
    if (t < 80) sW1[t] = W1[t];
    if (t < 16) { sb1[t] = b1[t]; sW2[t] = W2[t]; }
    __syncthreads();
    PDL_WAIT();

    int i = blockIdx.x * blockDim.x + t;
    if (i >= n) return;

    float di = g_dinv[i];
    uint4 w = *reinterpret_cast<const uint4*>(&g_aggh[i][0]);   // one 16B load
    float2 f0 = __half22float2(*reinterpret_cast<__half2*>(&w.x));
    float2 f1 = __half22float2(*reinterpret_cast<__half2*>(&w.y));
    float2 f2 = __half22float2(*reinterpret_cast<__half2*>(&w.z));
    float a[5] = {f0.x * di, f0.y * di, f1.x * di, f1.y * di, f2.x * di};

    float z = 0.0f;
    #pragma unroll
    for (int j = 0; j < 16; j++) {
        float h = sb1[j];
        #pragma unroll
        for (int k = 0; k < 5; k++) h = fmaf(a[k], sW1[k * 16 + j], h);
        h = fmaxf(h, 0.0f);          // relu
        z = fmaf(h, sW2[j], z);
    }
    float zs = z * di;
    g_zs[i] = zs;
    g_a2[i] = zs;                    // seed = self-loop
}

// Layer-2 aggregation: 1 edge/thread. Prelude: index loads (L2-resident by now).
__global__ void k_agg2(const int* __restrict__ ei, int E) {
    PDL_LAUNCH();
    int e = blockIdx.x * blockDim.x + threadIdx.x;
    if (e >= E) { PDL_WAIT(); return; }
    int s = ei[e];
    int d = ei[E + e];
    PDL_WAIT();
    atomicAdd(&g_a2[d], g_zs[s]);
}

// Final output.
__global__ void k_out(const float* __restrict__ b2, float* __restrict__ out, int n) {
    int i = blockIdx.x * blockDim.x + threadIdx.x;
    float bias = b2[0];              // input, pre-wait
    PDL_WAIT();
    if (i < n) out[i] = g_a2[i] * g_dinv[i] + bias;
}

static inline void launch_pdl(void* fn, dim3 grid, dim3 block,
                              void** args, bool pdl) {
    cudaLaunchConfig_t cfg = {};
    cfg.gridDim = grid;
    cfg.blockDim = block;
    cfg.stream = 0;
    cudaLaunchAttribute attr[1];
    if (pdl) {
        attr[0].id = cudaLaunchAttributeProgrammaticStreamSerialization;
        attr[0].val.programmaticStreamSerializationAllowed = 1;
        cfg.attrs = attr;
        cfg.numAttrs = 1;
    }
    cudaLaunchKernelExC(&cfg, fn, args);
}

extern "C" void kernel_launch(void* const* d_in, const int* in_sizes, int n_in,
                              void* d_out, int out_size) {
    const float* x  = (const float*)d_in[0];
    const int*   ei = (const int*)d_in[1];   // int32 (JAX x64-disabled canonicalizes int64)
    const float* W1 = (const float*)d_in[2];
    const float* b1 = (const float*)d_in[3];
    const float* W2 = (const float*)d_in[4];
    const float* b2 = (const float*)d_in[5];
    float* out = (float*)d_out;

    int n = in_sizes[0] / 5;
    int E = in_sizes[1] / 2;

    dim3 blk(TPB), blkn(TPB_N);
    dim3 g_e4(((E + 3) / 4 + TPB - 1) / TPB);
    dim3 g_e ((E + TPB - 1) / TPB);
    dim3 g_n ((n + TPB - 1) / TPB);
    dim3 g_nn((n + TPB_N - 1) / TPB_N);

    const int* dstp = ei + E;
    void* a_deg[]  = {(void*)&dstp, (void*)&E};
    void* a_prep[] = {(void*)&x, (void*)&n};
    void* a_agg1[] = {(void*)&ei, (void*)&E};
    void* a_node[] = {(void*)&W1, (void*)&b1, (void*)&W2, (void*)&n};
    void* a_agg2[] = {(void*)&ei, (void*)&E};
    void* a_out[]  = {(void*)&b2, (void*)&out, (void*)&n};

    launch_pdl((void*)k_degree, g_e4, blk,  a_deg,  false);
    launch_pdl((void*)k_prep,   g_n,  blk,  a_prep, true);
    launch_pdl((void*)k_agg1,   g_e,  blk,  a_agg1, true);
    launch_pdl((void*)k_node,   g_nn, blkn, a_node, true);
    launch_pdl((void*)k_agg2,   g_e,  blk,  a_agg2, true);
    launch_pdl((void*)k_out,    g_n,  blk,  a_out,  true);
}

// round 16
// speedup vs baseline: 1.0078x; 1.0078x over previous
#include <cuda_runtime.h>
#include <cuda_fp16.h>

#define N_MAX 100000
#define TPB   256
#define TPB_N 128

// Scratch (allocation-free rule: __device__ globals).
// fp16 rows of 8 (16B): slots 0..4 = features, 5..7 stay zero.
__device__ __align__(16) __half g_yh[N_MAX][8];    // pre-scaled features x*dinv (fp16)
__device__ __align__(16) __half g_aggh[N_MAX][8];  // layer-1 aggregation (fp16)
__device__ int   g_deg[N_MAX];                     // zero at entry (reset in k_prep)
__device__ float g_dinv[N_MAX];
__device__ float g_zs[N_MAX];                      // gather source (layer-2 scalar * dinv)
__device__ float g_a2[N_MAX];                      // RED target (layer-2 aggregation)
// NOTE: g_zs and g_a2 deliberately SEPARATE arrays — R13 showed colocating the
// gather source and RED target in one float2 costs ~7 us (same-sector contention).

// PDL: let the next grid launch early; wait gates on full predecessor completion.
#define PDL_LAUNCH() asm volatile("griddepcontrol.launch_dependents;" ::: "memory")
#define PDL_WAIT()   asm volatile("griddepcontrol.wait;" ::: "memory")

__device__ __forceinline__ unsigned h2_bits(__half2 h) {
    return *reinterpret_cast<unsigned*>(&h);
}

// One 128-bit vector half-precision reduction: 8 halves in a single op (4 LTS lanes).
__device__ __forceinline__ void red_add_v4_f16x2(void* addr, uint4 w) {
    asm volatile("red.global.add.noftz.v4.f16x2 [%0], {%1, %2, %3, %4};"
                 :: "l"(addr), "r"(w.x), "r"(w.y), "r"(w.z), "r"(w.w) : "memory");
}

// Degree: 1 edge/thread (R11 lesson: batched back-to-back random REDs contend
// in the L1tex queue; un-batched issue is faster for pure-RED kernels too).
__global__ void k_degree(const int* __restrict__ dst, int E) {
    PDL_LAUNCH();
    int e = blockIdx.x * blockDim.x + threadIdx.x;
    if (e >= E) return;
    atomicAdd(&g_deg[dst[e]], 1);
}

// dinv, pre-scaled fp16 features, seed layer-1 agg with the self-loop term.
// Prelude (pre-wait): load x (pure input). Post-wait: read+reset g_deg.
__global__ void k_prep(const float* __restrict__ x, int n) {
    PDL_LAUNCH();
    int i = blockIdx.x * blockDim.x + threadIdx.x;
    if (i >= n) { PDL_WAIT(); return; }
    const float* xi = x + (long)i * 5;
    float x0 = xi[0], x1 = xi[1], x2 = xi[2], x3 = xi[3], x4 = xi[4];
    PDL_WAIT();
    float di = rsqrtf((float)(g_deg[i] + 1));   // +1 = self-loop
    g_deg[i] = 0;                               // restore for next launch (determinism)
    g_dinv[i] = di;
    __half2 p0 = __floats2half2_rn(x0 * di, x1 * di);
    __half2 p1 = __floats2half2_rn(x2 * di, x3 * di);
    __half2 p2 = __floats2half2_rn(x4 * di, 0.f);
    uint4 w = make_uint4(h2_bits(p0), h2_bits(p1), h2_bits(p2), 0u);
    *reinterpret_cast<uint4*>(&g_yh[i][0])   = w;
    *reinterpret_cast<uint4*>(&g_aggh[i][0]) = w;   // seed = self-loop
}

// Layer-1 aggregation: 1 edge/thread (LTS-lane floor config).
// Prelude: index loads (pure inputs) overlap the tail of k_prep.
__global__ void k_agg1(const int* __restrict__ ei, int E) {
    PDL_LAUNCH();
    int e = blockIdx.x * blockDim.x + threadIdx.x;
    if (e >= E) { PDL_WAIT(); return; }
    int s = ei[e];                   // src  (input, pre-wait)
    int d = ei[E + e];               // dst  (input, pre-wait)
    PDL_WAIT();
    uint4 w = *reinterpret_cast<const uint4*>(&g_yh[s][0]);  // 16B gather, 1 wavefront
    red_add_v4_f16x2(&g_aggh[d][0], w);                      // 1 RED, 4 LTS lanes
}

// Per-node: finish layer-1 norm (x dinv), 5->16 GEMM + bias + relu, 16->1 GEMM.
// Prelude: weights (inputs) AND g_dinv — dinv was finalized by k_prep, which
// completed before agg1 (our gating predecessor) even started: transitively safe.
__global__ void k_node(const float* __restrict__ W1, const float* __restrict__ b1,
                       const float* __restrict__ W2, int n) {
    PDL_LAUNCH();
    __shared__ float sW1[80];
    __shared__ float sb1[16];
    __shared__ float sW2[16];
    int t = threadIdx.x;
    if (t < 80) sW1[t] = W1[t];
    if (t < 16) { sb1[t] = b1[t]; sW2[t] = W2[t]; }
    int i = blockIdx.x * blockDim.x + t;
    float di = (i < n) ? g_dinv[i] : 0.f;   // pre-wait (prep-complete by transitivity)
    __syncthreads();
    PDL_WAIT();

    if (i >= n) return;

    uint4 w = *reinterpret_cast<const uint4*>(&g_aggh[i][0]);   // one 16B load
    float2 f0 = __half22float2(*reinterpret_cast<__half2*>(&w.x));
    float2 f1 = __half22float2(*reinterpret_cast<__half2*>(&w.y));
    float2 f2 = __half22float2(*reinterpret_cast<__half2*>(&w.z));
    float a[5] = {f0.x * di, f0.y * di, f1.x * di, f1.y * di, f2.x * di};

    float z = 0.0f;
    #pragma unroll
    for (int j = 0; j < 16; j++) {
        float h = sb1[j];
        #pragma unroll
        for (int k = 0; k < 5; k++) h = fmaf(a[k], sW1[k * 16 + j], h);
        h = fmaxf(h, 0.0f);          // relu
        z = fmaf(h, sW2[j], z);
    }
    float zs = z * di;
    g_zs[i] = zs;
    g_a2[i] = zs;                    // seed = self-loop
}

// Layer-2 aggregation: 1 edge/thread. Prelude: index loads.
__global__ void k_agg2(const int* __restrict__ ei, int E) {
    PDL_LAUNCH();
    int e = blockIdx.x * blockDim.x + threadIdx.x;
    if (e >= E) { PDL_WAIT(); return; }
    int s = ei[e];
    int d = ei[E + e];
    PDL_WAIT();
    atomicAdd(&g_a2[d], g_zs[s]);
}

// Final output. dinv readable pre-wait (prep completed long before agg2 started).
__global__ void k_out(const float* __restrict__ b2, float* __restrict__ out, int n) {
    int i = blockIdx.x * blockDim.x + threadIdx.x;
    float bias = b2[0];                     // input, pre-wait
    float di = (i < n) ? g_dinv[i] : 0.f;   // pre-wait (transitively safe)
    PDL_WAIT();
    if (i < n) out[i] = g_a2[i] * di + bias;
}

static inline void launch_pdl(void* fn, dim3 grid, dim3 block,
                              void** args, bool pdl) {
    cudaLaunchConfig_t cfg = {};
    cfg.gridDim = grid;
    cfg.blockDim = block;
    cfg.stream = 0;
    cudaLaunchAttribute attr[1];
    if (pdl) {
        attr[0].id = cudaLaunchAttributeProgrammaticStreamSerialization;
        attr[0].val.programmaticStreamSerializationAllowed = 1;
        cfg.attrs = attr;
        cfg.numAttrs = 1;
    }
    cudaLaunchKernelExC(&cfg, fn, args);
}

extern "C" void kernel_launch(void* const* d_in, const int* in_sizes, int n_in,
                              void* d_out, int out_size) {
    const float* x  = (const float*)d_in[0];
    const int*   ei = (const int*)d_in[1];   // int32 (JAX x64-disabled canonicalizes int64)
    const float* W1 = (const float*)d_in[2];
    const float* b1 = (const float*)d_in[3];
    const float* W2 = (const float*)d_in[4];
    const float* b2 = (const float*)d_in[5];
    float* out = (float*)d_out;

    int n = in_sizes[0] / 5;
    int E = in_sizes[1] / 2;

    dim3 blk(TPB), blkn(TPB_N);
    dim3 g_e ((E + TPB - 1) / TPB);
    dim3 g_n ((n + TPB - 1) / TPB);
    dim3 g_nn((n + TPB_N - 1) / TPB_N);

    const int* dstp = ei + E;
    void* a_deg[]  = {(void*)&dstp, (void*)&E};
    void* a_prep[] = {(void*)&x, (void*)&n};
    void* a_agg1[] = {(void*)&ei, (void*)&E};
    void* a_node[] = {(void*)&W1, (void*)&b1, (void*)&W2, (void*)&n};
    void* a_agg2[] = {(void*)&ei, (void*)&E};
    void* a_out[]  = {(void*)&b2, (void*)&out, (void*)&n};

    launch_pdl((void*)k_degree, g_e,  blk,  a_deg,  false);
    launch_pdl((void*)k_prep,   g_n,  blk,  a_prep, true);
    launch_pdl((void*)k_agg1,   g_e,  blk,  a_agg1, true);
    launch_pdl((void*)k_node,   g_nn, blkn, a_node, true);
    launch_pdl((void*)k_agg2,   g_e,  blk,  a_agg2, true);
    launch_pdl((void*)k_out,    g_n,  blk,  a_out,  true);
}

// round 17
// speedup vs baseline: 1.0176x; 1.0098x over previous
#include <cuda_runtime.h>
#include <cuda_fp16.h>

#define N_MAX 100000
#define TPB_E 512
#define TPB   256
#define TPB_N 128

// Scratch (allocation-free rule: __device__ globals).
// fp16 rows of 8 (16B): slots 0..4 = features, 5..7 stay zero.
__device__ __align__(16) __half g_yh[N_MAX][8];    // pre-scaled features x*dinv (fp16)
__device__ __align__(16) __half g_aggh[N_MAX][8];  // layer-1 aggregation (fp16)
__device__ int   g_deg[N_MAX];                     // zero at entry (reset in k_prep)
__device__ float g_dinv[N_MAX];
__device__ float g_zs[N_MAX];                      // gather source (layer-2 scalar * dinv)
__device__ float g_a2[N_MAX];                      // RED target (layer-2 aggregation)
// NOTE: g_zs and g_a2 deliberately SEPARATE arrays — R13 showed colocating the
// gather source and RED target in one float2 costs ~7 us (same-sector contention).

// PDL: let the next grid launch early; wait gates on full predecessor completion.
#define PDL_LAUNCH() asm volatile("griddepcontrol.launch_dependents;" ::: "memory")
#define PDL_WAIT()   asm volatile("griddepcontrol.wait;" ::: "memory")

__device__ __forceinline__ unsigned h2_bits(__half2 h) {
    return *reinterpret_cast<unsigned*>(&h);
}

// One 128-bit vector half-precision reduction: 8 halves in a single op (4 LTS lanes).
__device__ __forceinline__ void red_add_v4_f16x2(void* addr, uint4 w) {
    asm volatile("red.global.add.noftz.v4.f16x2 [%0], {%1, %2, %3, %4};"
                 :: "l"(addr), "r"(w.x), "r"(w.y), "r"(w.z), "r"(w.w) : "memory");
}

// Degree: 1 edge/thread (R11 lesson: batched back-to-back random REDs contend
// in the L1tex queue; un-batched issue is faster for pure-RED kernels too).
__global__ void k_degree(const int* __restrict__ dst, int E) {
    PDL_LAUNCH();
    int e = blockIdx.x * blockDim.x + threadIdx.x;
    if (e >= E) return;
    atomicAdd(&g_deg[dst[e]], 1);
}

// dinv, pre-scaled fp16 features, seed layer-1 agg with the self-loop term.
// Prelude (pre-wait): load x (pure input). Post-wait: read+reset g_deg.
__global__ void k_prep(const float* __restrict__ x, int n) {
    PDL_LAUNCH();
    int i = blockIdx.x * blockDim.x + threadIdx.x;
    if (i >= n) { PDL_WAIT(); return; }
    const float* xi = x + (long)i * 5;
    float x0 = xi[0], x1 = xi[1], x2 = xi[2], x3 = xi[3], x4 = xi[4];
    PDL_WAIT();
    float di = rsqrtf((float)(g_deg[i] + 1));   // +1 = self-loop
    g_deg[i] = 0;                               // restore for next launch (determinism)
    g_dinv[i] = di;
    __half2 p0 = __floats2half2_rn(x0 * di, x1 * di);
    __half2 p1 = __floats2half2_rn(x2 * di, x3 * di);
    __half2 p2 = __floats2half2_rn(x4 * di, 0.f);
    uint4 w = make_uint4(h2_bits(p0), h2_bits(p1), h2_bits(p2), 0u);
    *reinterpret_cast<uint4*>(&g_yh[i][0])   = w;
    *reinterpret_cast<uint4*>(&g_aggh[i][0]) = w;   // seed = self-loop
}

// Layer-1 aggregation: 1 edge/thread (LTS-lane floor config).
// Prelude: index loads (pure inputs) overlap the tail of k_prep.
__global__ void k_agg1(const int* __restrict__ ei, int E) {
    PDL_LAUNCH();
    int e = blockIdx.x * blockDim.x + threadIdx.x;
    if (e >= E) { PDL_WAIT(); return; }
    int s = ei[e];                   // src  (input, pre-wait)
    int d = ei[E + e];               // dst  (input, pre-wait)
    PDL_WAIT();
    uint4 w = *reinterpret_cast<const uint4*>(&g_yh[s][0]);  // 16B gather, 1 wavefront
    red_add_v4_f16x2(&g_aggh[d][0], w);                      // 1 RED, 4 LTS lanes
}

// Per-node: finish layer-1 norm (x dinv), 5->16 GEMM + bias + relu, 16->1 GEMM.
// Prelude: weights (inputs) AND g_dinv — dinv was finalized by k_prep, which
// completed before agg1 (our gating predecessor) even started: transitively safe.
__global__ void k_node(const float* __restrict__ W1, const float* __restrict__ b1,
                       const float* __restrict__ W2, int n) {
    PDL_LAUNCH();
    __shared__ float sW1[80];
    __shared__ float sb1[16];
    __shared__ float sW2[16];
    int t = threadIdx.x;
    if (t < 80) sW1[t] = W1[t];
    if (t < 16) { sb1[t] = b1[t]; sW2[t] = W2[t]; }
    int i = blockIdx.x * blockDim.x + t;
    float di = (i < n) ? g_dinv[i] : 0.f;   // pre-wait (prep-complete by transitivity)
    __syncthreads();
    PDL_WAIT();

    if (i >= n) return;

    uint4 w = *reinterpret_cast<const uint4*>(&g_aggh[i][0]);   // one 16B load
    float2 f0 = __half22float2(*reinterpret_cast<__half2*>(&w.x));
    float2 f1 = __half22float2(*reinterpret_cast<__half2*>(&w.y));
    float2 f2 = __half22float2(*reinterpret_cast<__half2*>(&w.z));
    float a[5] = {f0.x * di, f0.y * di, f1.x * di, f1.y * di, f2.x * di};

    float z = 0.0f;
    #pragma unroll
    for (int j = 0; j < 16; j++) {
        float h = sb1[j];
        #pragma unroll
        for (int k = 0; k < 5; k++) h = fmaf(a[k], sW1[k * 16 + j], h);
        h = fmaxf(h, 0.0f);          // relu
        z = fmaf(h, sW2[j], z);
    }
    float zs = z * di;
    g_zs[i] = zs;
    g_a2[i] = zs;                    // seed = self-loop
}

// Layer-2 aggregation: 1 edge/thread. Prelude: index loads.
__global__ void k_agg2(const int* __restrict__ ei, int E) {
    PDL_LAUNCH();
    int e = blockIdx.x * blockDim.x + threadIdx.x;
    if (e >= E) { PDL_WAIT(); return; }
    int s = ei[e];
    int d = ei[E + e];
    PDL_WAIT();
    atomicAdd(&g_a2[d], g_zs[s]);
}

// Final output. dinv readable pre-wait (prep completed long before agg2 started).
__global__ void k_out(const float* __restrict__ b2, float* __restrict__ out, int n) {
    int i = blockIdx.x * blockDim.x + threadIdx.x;
    float bias = b2[0];                     // input, pre-wait
    float di = (i < n) ? g_dinv[i] : 0.f;   // pre-wait (transitively safe)
    PDL_WAIT();
    if (i < n) out[i] = g_a2[i] * di + bias;
}

static inline void launch_pdl(void* fn, dim3 grid, dim3 block,
                              void** args, bool pdl) {
    cudaLaunchConfig_t cfg = {};
    cfg.gridDim = grid;
    cfg.blockDim = block;
    cfg.stream = 0;
    cudaLaunchAttribute attr[1];
    if (pdl) {
        attr[0].id = cudaLaunchAttributeProgrammaticStreamSerialization;
        attr[0].val.programmaticStreamSerializationAllowed = 1;
        cfg.attrs = attr;
        cfg.numAttrs = 1;
    }
    cudaLaunchKernelExC(&cfg, fn, args);
}

extern "C" void kernel_launch(void* const* d_in, const int* in_sizes, int n_in,
                              void* d_out, int out_size) {
    const float* x  = (const float*)d_in[0];
    const int*   ei = (const int*)d_in[1];   // int32 (JAX x64-disabled canonicalizes int64)
    const float* W1 = (const float*)d_in[2];
    const float* b1 = (const float*)d_in[3];
    const float* W2 = (const float*)d_in[4];
    const float* b2 = (const float*)d_in[5];
    float* out = (float*)d_out;

    int n = in_sizes[0] / 5;
    int E = in_sizes[1] / 2;

    dim3 blke(TPB_E), blk(TPB), blkn(TPB_N);
    dim3 g_e ((E + TPB_E - 1) / TPB_E);
    dim3 g_n ((n + TPB - 1) / TPB);
    dim3 g_nn((n + TPB_N - 1) / TPB_N);

    const int* dstp = ei + E;
    void* a_deg[]  = {(void*)&dstp, (void*)&E};
    void* a_prep[] = {(void*)&x, (void*)&n};
    void* a_agg1[] = {(void*)&ei, (void*)&E};
    void* a_node[] = {(void*)&W1, (void*)&b1, (void*)&W2, (void*)&n};
    void* a_agg2[] = {(void*)&ei, (void*)&E};
    void* a_out[]  = {(void*)&b2, (void*)&out, (void*)&n};

    launch_pdl((void*)k_degree, g_e,  blke, a_deg,  false);
    launch_pdl((void*)k_prep,   g_n,  blk,  a_prep, true);
    launch_pdl((void*)k_agg1,   g_e,  blke, a_agg1, true);
    launch_pdl((void*)k_node,   g_nn, blkn, a_node, true);
    launch_pdl((void*)k_agg2,   g_e,  blke, a_agg2, true);
    launch_pdl((void*)k_out,    g_n,  blk,  a_out,  true);
}